// round 9
// baseline (speedup 1.0000x reference)
#include <cuda_runtime.h>
#include <math.h>

typedef unsigned long long u64;

// Problem constants
#define BB 256
#define TT 512
#define HH 128
#define VV 29275
#define G3 384          // 3*H
#define GN 192          // N columns per CTA (half of 384)
#define GMR 128         // M rows per tile
#define ASTRIDE 132     // padded A-tile row stride (floats)
#define NCTA 148

// Scratch (static device globals — no runtime allocation)
__device__ float g_G0[VV * G3];        // emb @ Wih0^T + b_ih0   (~45 MB)
__device__ float g_h0[BB * TT * HH];   // layer-0 hidden outputs (~64 MB)
__device__ float g_gx1[BB * TT * G3];  // h0 @ Wih1^T + b_ih1    (~201 MB)
__device__ float g_hlast[BB * HH];     // layer-1 final hidden

// ---------------------------------------------------------------------------
// f32x2 packed helpers
// ---------------------------------------------------------------------------
__device__ __forceinline__ u64 ffma2(u64 a, u64 b, u64 c) {
    u64 d;
    asm("fma.rn.f32x2 %0, %1, %2, %3;" : "=l"(d) : "l"(a), "l"(b), "l"(c));
    return d;
}
__device__ __forceinline__ u64 fadd2(u64 a, u64 b) {
    u64 d;
    asm("add.rn.f32x2 %0, %1, %2;" : "=l"(d) : "l"(a), "l"(b));
    return d;
}
__device__ __forceinline__ float2 unpk(u64 v) {
    float2 r;
    asm("mov.b64 {%0, %1}, %2;" : "=f"(r.x), "=f"(r.y) : "l"(v));
    return r;
}
__device__ __forceinline__ u64 dup2(float f) {
    u64 d;
    asm("mov.b64 %0, {%1, %1};" : "=l"(d) : "f"(f));
    return d;
}

// single-MUFU activations
__device__ __forceinline__ float mtanh(float v) {
    float r;
    asm("tanh.approx.f32 %0, %1;" : "=f"(r) : "f"(v));
    return r;
}
__device__ __forceinline__ float msig(float v) {
    return fmaf(0.5f, mtanh(0.5f * v), 0.5f);
}

// ---------------------------------------------------------------------------
// Register-tiled persistent GEMM: OUT[m, j] = bias[j] + sum_k A[m,k]*W[j,k]
// 148 CTAs: 74 per N-half (192 cols). W-half transposed once into Ws[k][192];
// per tile A transposed into As[k][132]. 384 threads; thread (a = tid&15,
// b = tid>>4) computes an 8m x 8j register block. Warp = 16 a-values x 2
// b-values -> W-frag LDS near-broadcast, A-frag 2 wf. k-loop software-
// pipelined: frags for k+1 prefetched while computing k.
// mode 0: A = A_ext (emb) -> g_G0 ;  mode 1: A = g_h0 -> g_gx1
// ---------------------------------------------------------------------------
__global__ void __launch_bounds__(384, 1)
gemm_tile(const float* __restrict__ A_ext, const float* __restrict__ W,
          const float* __restrict__ bias, int M, int mode)
{
    extern __shared__ float sm[];
    float* __restrict__ Ws = sm;               // [128][192]  96 KB
    float* __restrict__ As = sm + HH * GN;     // [128][132]  66 KB

    const float* __restrict__ A = mode ? g_h0 : A_ext;
    float* __restrict__ OUT     = mode ? g_gx1 : g_G0;

    const int tid   = threadIdx.x;
    const int nh    = (blockIdx.x >= 74) ? 1 : 0;
    const int cta   = nh ? (blockIdx.x - 74) : blockIdx.x;  // 0..73
    const int jbase = nh * GN;

    // one-time W stage (transposed): Ws[k][j] = W[(jbase+j)*128 + k]
    for (int idx = tid; idx < GN * 32; idx += 384) {
        int jj = idx >> 5, kq = idx & 31;
        float4 w = ((const float4*)(W + (jbase + jj) * HH))[kq];
        Ws[(4 * kq + 0) * GN + jj] = w.x;
        Ws[(4 * kq + 1) * GN + jj] = w.y;
        Ws[(4 * kq + 2) * GN + jj] = w.z;
        Ws[(4 * kq + 3) * GN + jj] = w.w;
    }

    const int a = tid & 15;            // m-group 0..15 (varies within warp)
    const int b = tid >> 4;            // j-group 0..23 (2 per warp)
    float bias8[8];
#pragma unroll
    for (int jj = 0; jj < 8; jj++) bias8[jj] = bias[jbase + b * 8 + jj];

    const float* __restrict__ Ab = As + a * 8;
    const float* __restrict__ Wb = Ws + b * 8;

    const int ntiles = (M + GMR - 1) / GMR;
    for (int mt = cta; mt < ntiles; mt += 74) {
        __syncthreads();   // As free of previous readers; also orders Ws stage
        // stage A tile transposed: As[k][m] = A[(mt*128+m)*128 + k]
        for (int idx = tid; idx < GMR * 32; idx += 384) {
            int m = idx >> 5, kq = idx & 31;
            int mm = mt * GMR + m;
            float4 v = make_float4(0.f, 0.f, 0.f, 0.f);
            if (mm < M) v = ((const float4*)(A + (size_t)mm * HH))[kq];
            As[(4 * kq + 0) * ASTRIDE + m] = v.x;
            As[(4 * kq + 1) * ASTRIDE + m] = v.y;
            As[(4 * kq + 2) * ASTRIDE + m] = v.z;
            As[(4 * kq + 3) * ASTRIDE + m] = v.w;
        }
        __syncthreads();

        u64 acc[8][4];
#pragma unroll
        for (int m = 0; m < 8; m++)
#pragma unroll
            for (int p = 0; p < 4; p++) acc[m][p] = 0ull;

        // k-pipelined mainloop: prefetch frag(k+1) while computing frag(k)
        float4 af0 = *(const float4*)(Ab);
        float4 af1 = *(const float4*)(Ab + 4);
        ulonglong2 wA = *(const ulonglong2*)(Wb);
        ulonglong2 wB = *(const ulonglong2*)(Wb + 4);

#pragma unroll 4
        for (int k = 0; k < HH - 1; k++) {
            float4 naf0 = *(const float4*)(Ab + (k + 1) * ASTRIDE);
            float4 naf1 = *(const float4*)(Ab + (k + 1) * ASTRIDE + 4);
            ulonglong2 nwA = *(const ulonglong2*)(Wb + (k + 1) * GN);
            ulonglong2 nwB = *(const ulonglong2*)(Wb + (k + 1) * GN + 4);

            float av[8] = {af0.x, af0.y, af0.z, af0.w,
                           af1.x, af1.y, af1.z, af1.w};
#pragma unroll
            for (int m = 0; m < 8; m++) {
                u64 am = dup2(av[m]);
                acc[m][0] = ffma2(am, wA.x, acc[m][0]);
                acc[m][1] = ffma2(am, wA.y, acc[m][1]);
                acc[m][2] = ffma2(am, wB.x, acc[m][2]);
                acc[m][3] = ffma2(am, wB.y, acc[m][3]);
            }
            af0 = naf0; af1 = naf1; wA = nwA; wB = nwB;
        }
        {   // peeled last k
            float av[8] = {af0.x, af0.y, af0.z, af0.w,
                           af1.x, af1.y, af1.z, af1.w};
#pragma unroll
            for (int m = 0; m < 8; m++) {
                u64 am = dup2(av[m]);
                acc[m][0] = ffma2(am, wA.x, acc[m][0]);
                acc[m][1] = ffma2(am, wA.y, acc[m][1]);
                acc[m][2] = ffma2(am, wB.x, acc[m][2]);
                acc[m][3] = ffma2(am, wB.y, acc[m][3]);
            }
        }

        // epilogue: 8 rows x 8 cols, 2 STG.128 per row
#pragma unroll
        for (int m = 0; m < 8; m++) {
            int mm = mt * GMR + a * 8 + m;
            if (mm < M) {
                float2 s0 = unpk(acc[m][0]);
                float2 s1 = unpk(acc[m][1]);
                float2 s2 = unpk(acc[m][2]);
                float2 s3 = unpk(acc[m][3]);
                float4 o0 = make_float4(bias8[0] + s0.x, bias8[1] + s0.y,
                                        bias8[2] + s1.x, bias8[3] + s1.y);
                float4 o1 = make_float4(bias8[4] + s2.x, bias8[5] + s2.y,
                                        bias8[6] + s3.x, bias8[7] + s3.y);
                float4* op = (float4*)(OUT + (size_t)mm * G3 + jbase + b * 8);
                op[0] = o0;
                op[1] = o1;
            }
        }
    }
}

// ---------------------------------------------------------------------------
// Persistent GRU scan (R6 exact — known-good 604us).
// 128 CTAs x 384 threads, 2 batch rows per CTA. Thread j: gate row j, both rows.
// Whh row j: k[0,96) in 48 u64 regs, k[96,128) in SMEM.
// Roles: j<128 r-threads (+row-1 update), 128..255 z-threads,
// 256..383 n-threads (publish gh1, row-0 update).
// ---------------------------------------------------------------------------
__global__ void __launch_bounds__(G3, 1)
gru_scan(const float* __restrict__ Whh, const float* __restrict__ bhh,
         const int* __restrict__ x, int layer)
{
    extern __shared__ ulonglong2 Wsm2[];            // 8*384 ulonglong2 = 48 KB
    __shared__ __align__(16) float hbuf[2][2][HH];  // [buf][row][k]
    __shared__ float2 rp[HH], zp[HH];
    __shared__ float  ghn1[HH];                     // n-thread's gh1 for r tail
    __shared__ int    xs[2][TT];

    const int j  = threadIdx.x;
    const int b0 = blockIdx.x * 2, b1 = b0 + 1;
    const float* __restrict__ gxT = layer ? g_gx1 : g_G0;

    // --- init ---
    u64 wreg[48];
    {
        const ulonglong2* __restrict__ Wr = (const ulonglong2*)(Whh + j * HH);
#pragma unroll
        for (int q = 0; q < 24; q++) {              // k = 0..95
            ulonglong2 w = Wr[q];
            wreg[2 * q]     = w.x;
            wreg[2 * q + 1] = w.y;
        }
#pragma unroll
        for (int q = 0; q < 8; q++)                 // k = 96..127
            Wsm2[q * G3 + j] = Wr[24 + q];
    }
    for (int i = j; i < 2 * TT; i += G3) {
        int r = i >> 9, t = i & (TT - 1);
        ((int*)xs)[i] = x[(b0 + r) * TT + t];
    }
    if (j < HH) { hbuf[0][0][j] = 0.0f; hbuf[0][1][j] = 0.0f; }
    const float bh = bhh[j];
    __syncthreads();

    // preload gx for t=0 (role-specialized; uniform per warp)
    float gxa = 0.0f, gxb = 0.0f, gxn1 = 0.0f;
    {
        if (layer == 0) {
            gxa = __ldg(&gxT[xs[0][0] * G3 + j]);
            if (j < 2 * HH) gxb = __ldg(&gxT[xs[1][0] * G3 + j]);
            if (j < HH)     gxn1 = __ldg(&gxT[xs[1][0] * G3 + j + 2 * HH]);
        } else {
            gxa = __ldg(&gxT[(b0 * TT) * G3 + j]);
            if (j < 2 * HH) gxb = __ldg(&gxT[(b1 * TT) * G3 + j]);
            if (j < HH)     gxn1 = __ldg(&gxT[(b1 * TT) * G3 + j + 2 * HH]);
        }
    }

    for (int t = 0; t < TT; t++) {
        const int buf = t & 1;

        // prefetch next step's input gates (role-specialized)
        float ngxa = 0.0f, ngxb = 0.0f, ngxn1 = 0.0f;
        if (t + 1 < TT) {
            if (layer == 0) {
                ngxa = __ldg(&gxT[xs[0][t + 1] * G3 + j]);
                if (j < 2 * HH) ngxb = __ldg(&gxT[xs[1][t + 1] * G3 + j]);
                if (j < HH)     ngxn1 = __ldg(&gxT[xs[1][t + 1] * G3 + j + 2 * HH]);
            } else {
                ngxa = __ldg(&gxT[(b0 * TT + t + 1) * G3 + j]);
                if (j < 2 * HH) ngxb = __ldg(&gxT[(b1 * TT + t + 1) * G3 + j]);
                if (j < HH)     ngxn1 = __ldg(&gxT[(b1 * TT + t + 1) * G3 + j + 2 * HH]);
            }
        }

        // gh[j] for both rows: packed k-pair dot product
        u64 a0 = 0ull, a1 = 0ull, a2 = 0ull, a3 = 0ull;
        const ulonglong2* __restrict__ h0p = (const ulonglong2*)hbuf[buf][0];
        const ulonglong2* __restrict__ h1p = (const ulonglong2*)hbuf[buf][1];
#pragma unroll
        for (int q = 0; q < 24; q++) {
            ulonglong2 ha = h0p[q];
            ulonglong2 hb = h1p[q];
            a0 = ffma2(wreg[2 * q],     ha.x, a0);
            a1 = ffma2(wreg[2 * q + 1], ha.y, a1);
            a2 = ffma2(wreg[2 * q],     hb.x, a2);
            a3 = ffma2(wreg[2 * q + 1], hb.y, a3);
        }
#pragma unroll
        for (int q = 0; q < 8; q++) {
            ulonglong2 w  = Wsm2[q * G3 + j];
            ulonglong2 ha = h0p[24 + q];
            ulonglong2 hb = h1p[24 + q];
            a0 = ffma2(w.x, ha.x, a0);
            a1 = ffma2(w.y, ha.y, a1);
            a2 = ffma2(w.x, hb.x, a2);
            a3 = ffma2(w.y, hb.y, a3);
        }
        float2 f0 = unpk(fadd2(a0, a1));
        float2 f1 = unpk(fadd2(a2, a3));
        const float gh0 = bh + (f0.x + f0.y);
        const float gh1 = bh + (f1.x + f1.y);

        // split roles
        if (j < HH) {
            // r-threads: produce r gates; after barrier do ROW-1 update
            float r0 = msig(gxa + gh0);
            float r1 = msig(gxb + gh1);
            rp[j] = make_float2(r0, r1);
            float hold1 = hbuf[buf][1][j];
            asm volatile("bar.sync 1, %0;" :: "n"(G3) : "memory");
            float z1 = zp[j].y;
            float g1 = ghn1[j];
            float n1 = mtanh(gxn1 + r1 * g1);
            float hn1 = n1 + z1 * (hold1 - n1);     // (1-z)*n + z*h
            hbuf[buf ^ 1][1][j] = hn1;
            if (layer == 0) {
                g_h0[(b1 * TT + t) * HH + j] = hn1;
            } else if (t == TT - 1) {
                g_hlast[b1 * HH + j] = hn1;
            }
        } else if (j < 2 * HH) {
            // z-threads: produce z gates, then idle
            zp[j - HH] = make_float2(msig(gxa + gh0), msig(gxb + gh1));
            asm volatile("bar.arrive 1, %0;" :: "n"(G3) : "memory");
        } else {
            // n-threads: publish gh1, after barrier do ROW-0 update
            const int i = j - 2 * HH;
            ghn1[i] = gh1;
            float hold0 = hbuf[buf][0][i];
            asm volatile("bar.sync 1, %0;" :: "n"(G3) : "memory");
            float2 rv = rp[i];
            float z0 = zp[i].x;
            float n0 = mtanh(gxa + rv.x * gh0);
            float hn0 = n0 + z0 * (hold0 - n0);
            hbuf[buf ^ 1][0][i] = hn0;
            if (layer == 0) {
                g_h0[(b0 * TT + t) * HH + i] = hn0;
            } else if (t == TT - 1) {
                g_hlast[b0 * HH + i] = hn0;
            }
        }
        __syncthreads();
        gxa = ngxa;
        gxb = ngxb;
        gxn1 = ngxn1;
    }
}

// ---------------------------------------------------------------------------
__global__ void __launch_bounds__(BB)
fc_kernel(const float* __restrict__ fcw, const float* __restrict__ fcb,
          float* __restrict__ out)
{
    __shared__ float ws[3 * HH];
    int b = threadIdx.x;
    for (int i = b; i < 3 * HH; i += BB) ws[i] = fcw[i];
    __syncthreads();
    float a0 = fcb[0], a1 = fcb[1], a2 = fcb[2];
#pragma unroll 4
    for (int k = 0; k < HH; k++) {
        float h = g_hlast[b * HH + k];
        h = h > 0.0f ? h : 0.0f;
        a0 = fmaf(h, ws[k], a0);
        a1 = fmaf(h, ws[HH + k], a1);
        a2 = fmaf(h, ws[2 * HH + k], a2);
    }
    out[b * 3 + 0] = a0;
    out[b * 3 + 1] = a1;
    out[b * 3 + 2] = a2;
}

// ---------------------------------------------------------------------------
extern "C" void kernel_launch(void* const* d_in, const int* in_sizes, int n_in,
                              void* d_out, int out_size)
{
    const int*   x    = (const int*)  d_in[0];
    const float* emb  = (const float*)d_in[1];
    const float* W_ih = (const float*)d_in[2];   // [2][384][128]
    const float* W_hh = (const float*)d_in[3];   // [2][384][128]
    const float* b_ih = (const float*)d_in[4];   // [2][384]
    const float* b_hh = (const float*)d_in[5];   // [2][384]
    const float* fc_w = (const float*)d_in[6];   // [3][128]
    const float* fc_b = (const float*)d_in[7];   // [3]
    float* out = (float*)d_out;

    const int smem_scan = 8 * G3 * (int)sizeof(ulonglong2);                // 48 KB
    const int smem_gemm = (HH * GN + HH * ASTRIDE) * (int)sizeof(float);   // ~162 KB
    cudaFuncSetAttribute(gru_scan, cudaFuncAttributeMaxDynamicSharedMemorySize,
                         smem_scan);
    cudaFuncSetAttribute(gemm_tile, cudaFuncAttributeMaxDynamicSharedMemorySize,
                         smem_gemm);

    // 1) G0 = emb @ Wih0^T + b_ih0  (vocab-side precompute: V < B*T)
    gemm_tile<<<NCTA, 384, smem_gemm>>>(emb, W_ih, b_ih, VV, 0);
    // 2) layer-0 scan (gx gathered from G0), writes g_h0
    gru_scan<<<BB / 2, G3, smem_scan>>>(W_hh, b_hh, x, 0);
    // 3) gx1 = h0 @ Wih1^T + b_ih1
    gemm_tile<<<NCTA, 384, smem_gemm>>>(nullptr, W_ih + G3 * HH, b_ih + G3, BB * TT, 1);
    // 4) layer-1 scan, writes g_hlast
    gru_scan<<<BB / 2, G3, smem_scan>>>(W_hh + G3 * HH, b_hh + G3, x, 1);
    // 5) head
    fc_kernel<<<1, BB>>>(fc_w, fc_b, out);
}

// round 11
// speedup vs baseline: 1.0263x; 1.0263x over previous
#include <cuda_runtime.h>
#include <math.h>

typedef unsigned long long u64;

// Problem constants
#define BB 256
#define TT 512
#define HH 128
#define VV 29275
#define G3 384          // 3*H
#define GN 192          // N columns per CTA (half of 384)
#define WSTRIDE 196     // padded Ws row stride (floats): 196*4 % 128B de-generates banks
#define GMR 128         // M rows per tile
#define ASTRIDE 132     // padded A-tile row stride (floats)
#define NCTA 148

// Scratch (static device globals — no runtime allocation)
__device__ float g_G0[VV * G3];        // emb @ Wih0^T + b_ih0   (~45 MB)
__device__ float g_h0[BB * TT * HH];   // layer-0 hidden outputs (~64 MB)
__device__ float g_gx1[BB * TT * G3];  // h0 @ Wih1^T + b_ih1    (~201 MB)
__device__ float g_hlast[BB * HH];     // layer-1 final hidden

// ---------------------------------------------------------------------------
// f32x2 packed helpers
// ---------------------------------------------------------------------------
__device__ __forceinline__ u64 ffma2(u64 a, u64 b, u64 c) {
    u64 d;
    asm("fma.rn.f32x2 %0, %1, %2, %3;" : "=l"(d) : "l"(a), "l"(b), "l"(c));
    return d;
}
__device__ __forceinline__ u64 fadd2(u64 a, u64 b) {
    u64 d;
    asm("add.rn.f32x2 %0, %1, %2;" : "=l"(d) : "l"(a), "l"(b));
    return d;
}
__device__ __forceinline__ float2 unpk(u64 v) {
    float2 r;
    asm("mov.b64 {%0, %1}, %2;" : "=f"(r.x), "=f"(r.y) : "l"(v));
    return r;
}
__device__ __forceinline__ u64 dup2(float f) {
    u64 d;
    asm("mov.b64 %0, {%1, %1};" : "=l"(d) : "f"(f));
    return d;
}

// single-MUFU activations
__device__ __forceinline__ float mtanh(float v) {
    float r;
    asm("tanh.approx.f32 %0, %1;" : "=f"(r) : "f"(v));
    return r;
}
__device__ __forceinline__ float msig(float v) {
    return fmaf(0.5f, mtanh(0.5f * v), 0.5f);
}

// within-quad row permutation for conflict-free-ish transpose staging:
// row' = 4*kq + ((c + kq) & 3). Applied to BOTH As and Ws staging, so row r
// holds the same k for A and W; compute loops iterate rows linearly.
__device__ __forceinline__ int prow(int kq, int c) {
    return 4 * kq + ((c + kq) & 3);
}

// ---------------------------------------------------------------------------
// Register-tiled persistent GEMM (R8 structure + pi-permuted staging).
// 148 CTAs: 74 per N-half (192 cols). W-half transposed once into
// Ws[row][WSTRIDE=196]; per tile A transposed into As[row][132].
// 384 threads = 16a x 24b (a = tid/24, b = tid%24); thread computes an
// 8m x 8j register block. mode 0: emb -> g_G0 ;  mode 1: g_h0 -> g_gx1
// ---------------------------------------------------------------------------
__global__ void __launch_bounds__(384, 1)
gemm_tile(const float* __restrict__ A_ext, const float* __restrict__ W,
          const float* __restrict__ bias, int M, int mode)
{
    extern __shared__ float sm[];
    float* __restrict__ Ws = sm;                   // [128][196]  100.4 KB
    float* __restrict__ As = sm + HH * WSTRIDE;    // [128][132]  66 KB

    const float* __restrict__ A = mode ? g_h0 : A_ext;
    float* __restrict__ OUT     = mode ? g_gx1 : g_G0;

    const int tid   = threadIdx.x;
    const int nh    = (blockIdx.x >= 74) ? 1 : 0;
    const int cta   = nh ? (blockIdx.x - 74) : blockIdx.x;  // 0..73
    const int jbase = nh * GN;

    // one-time W stage (transposed, pi-permuted rows)
    for (int idx = tid; idx < GN * 32; idx += 384) {
        int jj = idx >> 5, kq = idx & 31;
        float4 w = ((const float4*)(W + (jbase + jj) * HH))[kq];
        Ws[prow(kq, 0) * WSTRIDE + jj] = w.x;
        Ws[prow(kq, 1) * WSTRIDE + jj] = w.y;
        Ws[prow(kq, 2) * WSTRIDE + jj] = w.z;
        Ws[prow(kq, 3) * WSTRIDE + jj] = w.w;
    }

    const int a = tid / 24;            // m-group 0..15
    const int b = tid % 24;            // j-group 0..23
    float bias8[8];
#pragma unroll
    for (int jj = 0; jj < 8; jj++) bias8[jj] = bias[jbase + b * 8 + jj];

    const int ntiles = (M + GMR - 1) / GMR;
    for (int mt = cta; mt < ntiles; mt += 74) {
        __syncthreads();   // As free of previous readers; also orders Ws stage
        // stage A tile transposed (pi-permuted rows): row r holds k=invpi(r)
        for (int idx = tid; idx < GMR * 32; idx += 384) {
            int m = idx >> 5, kq = idx & 31;
            int mm = mt * GMR + m;
            float4 v = make_float4(0.f, 0.f, 0.f, 0.f);
            if (mm < M) v = ((const float4*)(A + (size_t)mm * HH))[kq];
            As[prow(kq, 0) * ASTRIDE + m] = v.x;
            As[prow(kq, 1) * ASTRIDE + m] = v.y;
            As[prow(kq, 2) * ASTRIDE + m] = v.z;
            As[prow(kq, 3) * ASTRIDE + m] = v.w;
        }
        __syncthreads();

        u64 acc[8][4];
#pragma unroll
        for (int m = 0; m < 8; m++)
#pragma unroll
            for (int p = 0; p < 4; p++) acc[m][p] = 0ull;

#pragma unroll 4
        for (int r = 0; r < HH; r++) {             // rows = permuted k; sum-all
            const float4 af0 = *(const float4*)(As + r * ASTRIDE + a * 8);
            const float4 af1 = *(const float4*)(As + r * ASTRIDE + a * 8 + 4);
            const ulonglong2* __restrict__ wp =
                (const ulonglong2*)(Ws + r * WSTRIDE + b * 8);
            ulonglong2 wA = wp[0], wB = wp[1];
            float av[8] = {af0.x, af0.y, af0.z, af0.w,
                           af1.x, af1.y, af1.z, af1.w};
#pragma unroll
            for (int m = 0; m < 8; m++) {
                u64 am = dup2(av[m]);
                acc[m][0] = ffma2(am, wA.x, acc[m][0]);
                acc[m][1] = ffma2(am, wA.y, acc[m][1]);
                acc[m][2] = ffma2(am, wB.x, acc[m][2]);
                acc[m][3] = ffma2(am, wB.y, acc[m][3]);
            }
        }

        // epilogue: 8 rows x 8 cols, 2 STG.128 per row
#pragma unroll
        for (int m = 0; m < 8; m++) {
            int mm = mt * GMR + a * 8 + m;
            if (mm < M) {
                float2 s0 = unpk(acc[m][0]);
                float2 s1 = unpk(acc[m][1]);
                float2 s2 = unpk(acc[m][2]);
                float2 s3 = unpk(acc[m][3]);
                float4 o0 = make_float4(bias8[0] + s0.x, bias8[1] + s0.y,
                                        bias8[2] + s1.x, bias8[3] + s1.y);
                float4 o1 = make_float4(bias8[4] + s2.x, bias8[5] + s2.y,
                                        bias8[6] + s3.x, bias8[7] + s3.y);
                float4* op = (float4*)(OUT + (size_t)mm * G3 + jbase + b * 8);
                op[0] = o0;
                op[1] = o1;
            }
        }
    }
}

// ---------------------------------------------------------------------------
// Persistent GRU scan (R6 structure + interleaved W-SMEM prefetch).
// 128 CTAs x 384 threads, 2 batch rows per CTA. Thread j: gate row j, both rows.
// Whh row j: k[0,96) in 48 u64 regs, k[96,128) in SMEM; the 8 SMEM W loads
// are issued one group ahead, interleaved 3 reg-iterations : 1 smem-iteration.
// Roles: j<128 r-threads (+row-1 update), 128..255 z-threads,
// 256..383 n-threads (publish gh1, row-0 update).
// ---------------------------------------------------------------------------
__global__ void __launch_bounds__(G3, 1)
gru_scan(const float* __restrict__ Whh, const float* __restrict__ bhh,
         const int* __restrict__ x, int layer)
{
    extern __shared__ ulonglong2 Wsm2[];            // 8*384 ulonglong2 = 48 KB
    __shared__ __align__(16) float hbuf[2][2][HH];  // [buf][row][k]
    __shared__ float2 rp[HH], zp[HH];
    __shared__ float  ghn1[HH];                     // n-thread's gh1 for r tail
    __shared__ int    xs[2][TT];

    const int j  = threadIdx.x;
    const int b0 = blockIdx.x * 2, b1 = b0 + 1;
    const float* __restrict__ gxT = layer ? g_gx1 : g_G0;

    // --- init ---
    u64 wreg[48];
    {
        const ulonglong2* __restrict__ Wr = (const ulonglong2*)(Whh + j * HH);
#pragma unroll
        for (int q = 0; q < 24; q++) {              // k = 0..95
            ulonglong2 w = Wr[q];
            wreg[2 * q]     = w.x;
            wreg[2 * q + 1] = w.y;
        }
#pragma unroll
        for (int q = 0; q < 8; q++)                 // k = 96..127
            Wsm2[q * G3 + j] = Wr[24 + q];
    }
    for (int i = j; i < 2 * TT; i += G3) {
        int r = i >> 9, t = i & (TT - 1);
        ((int*)xs)[i] = x[(b0 + r) * TT + t];
    }
    if (j < HH) { hbuf[0][0][j] = 0.0f; hbuf[0][1][j] = 0.0f; }
    const float bh = bhh[j];
    __syncthreads();

    // preload gx for t=0 (role-specialized; uniform per warp)
    float gxa = 0.0f, gxb = 0.0f, gxn1 = 0.0f;
    {
        if (layer == 0) {
            gxa = __ldg(&gxT[xs[0][0] * G3 + j]);
            if (j < 2 * HH) gxb = __ldg(&gxT[xs[1][0] * G3 + j]);
            if (j < HH)     gxn1 = __ldg(&gxT[xs[1][0] * G3 + j + 2 * HH]);
        } else {
            gxa = __ldg(&gxT[(b0 * TT) * G3 + j]);
            if (j < 2 * HH) gxb = __ldg(&gxT[(b1 * TT) * G3 + j]);
            if (j < HH)     gxn1 = __ldg(&gxT[(b1 * TT) * G3 + j + 2 * HH]);
        }
    }

    for (int t = 0; t < TT; t++) {
        const int buf = t & 1;

        // prefetch next step's input gates (role-specialized)
        float ngxa = 0.0f, ngxb = 0.0f, ngxn1 = 0.0f;
        if (t + 1 < TT) {
            if (layer == 0) {
                ngxa = __ldg(&gxT[xs[0][t + 1] * G3 + j]);
                if (j < 2 * HH) ngxb = __ldg(&gxT[xs[1][t + 1] * G3 + j]);
                if (j < HH)     ngxn1 = __ldg(&gxT[xs[1][t + 1] * G3 + j + 2 * HH]);
            } else {
                ngxa = __ldg(&gxT[(b0 * TT + t + 1) * G3 + j]);
                if (j < 2 * HH) ngxb = __ldg(&gxT[(b1 * TT + t + 1) * G3 + j]);
                if (j < HH)     ngxn1 = __ldg(&gxT[(b1 * TT + t + 1) * G3 + j + 2 * HH]);
            }
        }

        // gh[j] for both rows; 8 W-smem loads interleaved 3:1 with reg part,
        // issued one group ahead so each has ~18 instructions of cover.
        u64 a0 = 0ull, a1 = 0ull, a2 = 0ull, a3 = 0ull;
        const ulonglong2* __restrict__ h0p = (const ulonglong2*)hbuf[buf][0];
        const ulonglong2* __restrict__ h1p = (const ulonglong2*)hbuf[buf][1];
        ulonglong2 wcur = Wsm2[j];                  // group 0 (k = 96..99)
#pragma unroll
        for (int g = 0; g < 8; g++) {
            ulonglong2 wnxt = wcur;
            if (g < 7) wnxt = Wsm2[(g + 1) * G3 + j];
#pragma unroll
            for (int q = 3 * g; q < 3 * g + 3; q++) {
                ulonglong2 ha = h0p[q];
                ulonglong2 hb = h1p[q];
                a0 = ffma2(wreg[2 * q],     ha.x, a0);
                a1 = ffma2(wreg[2 * q + 1], ha.y, a1);
                a2 = ffma2(wreg[2 * q],     hb.x, a2);
                a3 = ffma2(wreg[2 * q + 1], hb.y, a3);
            }
            {
                ulonglong2 ha = h0p[24 + g];
                ulonglong2 hb = h1p[24 + g];
                a0 = ffma2(wcur.x, ha.x, a0);
                a1 = ffma2(wcur.y, ha.y, a1);
                a2 = ffma2(wcur.x, hb.x, a2);
                a3 = ffma2(wcur.y, hb.y, a3);
            }
            wcur = wnxt;
        }
        float2 f0 = unpk(fadd2(a0, a1));
        float2 f1 = unpk(fadd2(a2, a3));
        const float gh0 = bh + (f0.x + f0.y);
        const float gh1 = bh + (f1.x + f1.y);

        // split roles
        if (j < HH) {
            // r-threads: produce r gates; after barrier do ROW-1 update
            float r0 = msig(gxa + gh0);
            float r1 = msig(gxb + gh1);
            rp[j] = make_float2(r0, r1);
            float hold1 = hbuf[buf][1][j];
            asm volatile("bar.sync 1, %0;" :: "n"(G3) : "memory");
            float z1 = zp[j].y;
            float g1 = ghn1[j];
            float n1 = mtanh(gxn1 + r1 * g1);
            float hn1 = n1 + z1 * (hold1 - n1);     // (1-z)*n + z*h
            hbuf[buf ^ 1][1][j] = hn1;
            if (layer == 0) {
                g_h0[(b1 * TT + t) * HH + j] = hn1;
            } else if (t == TT - 1) {
                g_hlast[b1 * HH + j] = hn1;
            }
        } else if (j < 2 * HH) {
            // z-threads: produce z gates, then idle
            zp[j - HH] = make_float2(msig(gxa + gh0), msig(gxb + gh1));
            asm volatile("bar.arrive 1, %0;" :: "n"(G3) : "memory");
        } else {
            // n-threads: publish gh1, after barrier do ROW-0 update
            const int i = j - 2 * HH;
            ghn1[i] = gh1;
            float hold0 = hbuf[buf][0][i];
            asm volatile("bar.sync 1, %0;" :: "n"(G3) : "memory");
            float2 rv = rp[i];
            float z0 = zp[i].x;
            float n0 = mtanh(gxa + rv.x * gh0);
            float hn0 = n0 + z0 * (hold0 - n0);
            hbuf[buf ^ 1][0][i] = hn0;
            if (layer == 0) {
                g_h0[(b0 * TT + t) * HH + i] = hn0;
            } else if (t == TT - 1) {
                g_hlast[b0 * HH + i] = hn0;
            }
        }
        __syncthreads();
        gxa = ngxa;
        gxb = ngxb;
        gxn1 = ngxn1;
    }
}

// ---------------------------------------------------------------------------
__global__ void __launch_bounds__(BB)
fc_kernel(const float* __restrict__ fcw, const float* __restrict__ fcb,
          float* __restrict__ out)
{
    __shared__ float ws[3 * HH];
    int b = threadIdx.x;
    for (int i = b; i < 3 * HH; i += BB) ws[i] = fcw[i];
    __syncthreads();
    float a0 = fcb[0], a1 = fcb[1], a2 = fcb[2];
#pragma unroll 4
    for (int k = 0; k < HH; k++) {
        float h = g_hlast[b * HH + k];
        h = h > 0.0f ? h : 0.0f;
        a0 = fmaf(h, ws[k], a0);
        a1 = fmaf(h, ws[HH + k], a1);
        a2 = fmaf(h, ws[2 * HH + k], a2);
    }
    out[b * 3 + 0] = a0;
    out[b * 3 + 1] = a1;
    out[b * 3 + 2] = a2;
}

// ---------------------------------------------------------------------------
extern "C" void kernel_launch(void* const* d_in, const int* in_sizes, int n_in,
                              void* d_out, int out_size)
{
    const int*   x    = (const int*)  d_in[0];
    const float* emb  = (const float*)d_in[1];
    const float* W_ih = (const float*)d_in[2];   // [2][384][128]
    const float* W_hh = (const float*)d_in[3];   // [2][384][128]
    const float* b_ih = (const float*)d_in[4];   // [2][384]
    const float* b_hh = (const float*)d_in[5];   // [2][384]
    const float* fc_w = (const float*)d_in[6];   // [3][128]
    const float* fc_b = (const float*)d_in[7];   // [3]
    float* out = (float*)d_out;

    const int smem_scan = 8 * G3 * (int)sizeof(ulonglong2);                   // 48 KB
    const int smem_gemm = (HH * WSTRIDE + HH * ASTRIDE) * (int)sizeof(float); // ~166 KB
    cudaFuncSetAttribute(gru_scan, cudaFuncAttributeMaxDynamicSharedMemorySize,
                         smem_scan);
    cudaFuncSetAttribute(gemm_tile, cudaFuncAttributeMaxDynamicSharedMemorySize,
                         smem_gemm);

    // 1) G0 = emb @ Wih0^T + b_ih0  (vocab-side precompute: V < B*T)
    gemm_tile<<<NCTA, 384, smem_gemm>>>(emb, W_ih, b_ih, VV, 0);
    // 2) layer-0 scan (gx gathered from G0), writes g_h0
    gru_scan<<<BB / 2, G3, smem_scan>>>(W_hh, b_hh, x, 0);
    // 3) gx1 = h0 @ Wih1^T + b_ih1
    gemm_tile<<<NCTA, 384, smem_gemm>>>(nullptr, W_ih + G3 * HH, b_ih + G3, BB * TT, 1);
    // 4) layer-1 scan, writes g_hlast
    gru_scan<<<BB / 2, G3, smem_scan>>>(W_hh + G3 * HH, b_hh + G3, x, 1);
    // 5) head
    fc_kernel<<<1, BB>>>(fc_w, fc_b, out);
}

// round 12
// speedup vs baseline: 1.0452x; 1.0184x over previous
#include <cuda_runtime.h>
#include <math.h>

typedef unsigned long long u64;

// Problem constants
#define BB 256
#define TT 512
#define HH 128
#define VV 29275
#define G3 384          // 3*H
#define GN 192          // N columns per CTA (half of 384)
#define WSTRIDE 196     // padded Ws row stride (floats)
#define GMR 128         // M rows per tile
#define ASTRIDE 132     // padded A-tile row stride (floats)
#define NCTA 148

// Scratch (static device globals — no runtime allocation)
__device__ float g_G0[VV * G3];        // emb @ Wih0^T + b_ih0   (~45 MB)
__device__ float g_h0[BB * TT * HH];   // layer-0 hidden outputs (~64 MB)
__device__ float g_gx1[BB * TT * G3];  // h0 @ Wih1^T + b_ih1    (~201 MB)
__device__ float g_hlast[BB * HH];     // layer-1 final hidden

// ---------------------------------------------------------------------------
// f32x2 packed helpers
// ---------------------------------------------------------------------------
__device__ __forceinline__ u64 ffma2(u64 a, u64 b, u64 c) {
    u64 d;
    asm("fma.rn.f32x2 %0, %1, %2, %3;" : "=l"(d) : "l"(a), "l"(b), "l"(c));
    return d;
}
__device__ __forceinline__ u64 fadd2(u64 a, u64 b) {
    u64 d;
    asm("add.rn.f32x2 %0, %1, %2;" : "=l"(d) : "l"(a), "l"(b));
    return d;
}
__device__ __forceinline__ float2 unpk(u64 v) {
    float2 r;
    asm("mov.b64 {%0, %1}, %2;" : "=f"(r.x), "=f"(r.y) : "l"(v));
    return r;
}
__device__ __forceinline__ u64 dup2(float f) {
    u64 d;
    asm("mov.b64 %0, {%1, %1};" : "=l"(d) : "f"(f));
    return d;
}

// single-MUFU activations
__device__ __forceinline__ float mtanh(float v) {
    float r;
    asm("tanh.approx.f32 %0, %1;" : "=f"(r) : "f"(v));
    return r;
}
__device__ __forceinline__ float msig(float v) {
    return fmaf(0.5f, mtanh(0.5f * v), 0.5f);
}

// within-quad row permutation for conflict-free-ish transpose staging:
// row' = 4*kq + ((c + kq) & 3). Applied to BOTH As and Ws staging, so row r
// holds the same k for A and W; compute loops iterate rows linearly.
__device__ __forceinline__ int prow(int kq, int c) {
    return 4 * kq + ((c + kq) & 3);
}

// ---------------------------------------------------------------------------
// Register-tiled persistent GEMM (R11 exact — permuted staging, proven win).
// 148 CTAs: 74 per N-half (192 cols). W-half transposed once into
// Ws[row][WSTRIDE=196]; per tile A transposed into As[row][132].
// 384 threads = 16a x 24b (a = tid/24, b = tid%24); thread computes an
// 8m x 8j register block. mode 0: emb -> g_G0 ;  mode 1: g_h0 -> g_gx1
// ---------------------------------------------------------------------------
__global__ void __launch_bounds__(384, 1)
gemm_tile(const float* __restrict__ A_ext, const float* __restrict__ W,
          const float* __restrict__ bias, int M, int mode)
{
    extern __shared__ float sm[];
    float* __restrict__ Ws = sm;                   // [128][196]  100.4 KB
    float* __restrict__ As = sm + HH * WSTRIDE;    // [128][132]  66 KB

    const float* __restrict__ A = mode ? g_h0 : A_ext;
    float* __restrict__ OUT     = mode ? g_gx1 : g_G0;

    const int tid   = threadIdx.x;
    const int nh    = (blockIdx.x >= 74) ? 1 : 0;
    const int cta   = nh ? (blockIdx.x - 74) : blockIdx.x;  // 0..73
    const int jbase = nh * GN;

    // one-time W stage (transposed, pi-permuted rows)
    for (int idx = tid; idx < GN * 32; idx += 384) {
        int jj = idx >> 5, kq = idx & 31;
        float4 w = ((const float4*)(W + (jbase + jj) * HH))[kq];
        Ws[prow(kq, 0) * WSTRIDE + jj] = w.x;
        Ws[prow(kq, 1) * WSTRIDE + jj] = w.y;
        Ws[prow(kq, 2) * WSTRIDE + jj] = w.z;
        Ws[prow(kq, 3) * WSTRIDE + jj] = w.w;
    }

    const int a = tid / 24;            // m-group 0..15
    const int b = tid % 24;            // j-group 0..23
    float bias8[8];
#pragma unroll
    for (int jj = 0; jj < 8; jj++) bias8[jj] = bias[jbase + b * 8 + jj];

    const int ntiles = (M + GMR - 1) / GMR;
    for (int mt = cta; mt < ntiles; mt += 74) {
        __syncthreads();   // As free of previous readers; also orders Ws stage
        // stage A tile transposed (pi-permuted rows): row r holds k=invpi(r)
        for (int idx = tid; idx < GMR * 32; idx += 384) {
            int m = idx >> 5, kq = idx & 31;
            int mm = mt * GMR + m;
            float4 v = make_float4(0.f, 0.f, 0.f, 0.f);
            if (mm < M) v = ((const float4*)(A + (size_t)mm * HH))[kq];
            As[prow(kq, 0) * ASTRIDE + m] = v.x;
            As[prow(kq, 1) * ASTRIDE + m] = v.y;
            As[prow(kq, 2) * ASTRIDE + m] = v.z;
            As[prow(kq, 3) * ASTRIDE + m] = v.w;
        }
        __syncthreads();

        u64 acc[8][4];
#pragma unroll
        for (int m = 0; m < 8; m++)
#pragma unroll
            for (int p = 0; p < 4; p++) acc[m][p] = 0ull;

#pragma unroll 4
        for (int r = 0; r < HH; r++) {             // rows = permuted k; sum-all
            const float4 af0 = *(const float4*)(As + r * ASTRIDE + a * 8);
            const float4 af1 = *(const float4*)(As + r * ASTRIDE + a * 8 + 4);
            const ulonglong2* __restrict__ wp =
                (const ulonglong2*)(Ws + r * WSTRIDE + b * 8);
            ulonglong2 wA = wp[0], wB = wp[1];
            float av[8] = {af0.x, af0.y, af0.z, af0.w,
                           af1.x, af1.y, af1.z, af1.w};
#pragma unroll
            for (int m = 0; m < 8; m++) {
                u64 am = dup2(av[m]);
                acc[m][0] = ffma2(am, wA.x, acc[m][0]);
                acc[m][1] = ffma2(am, wA.y, acc[m][1]);
                acc[m][2] = ffma2(am, wB.x, acc[m][2]);
                acc[m][3] = ffma2(am, wB.y, acc[m][3]);
            }
        }

        // epilogue: 8 rows x 8 cols, 2 STG.128 per row
#pragma unroll
        for (int m = 0; m < 8; m++) {
            int mm = mt * GMR + a * 8 + m;
            if (mm < M) {
                float2 s0 = unpk(acc[m][0]);
                float2 s1 = unpk(acc[m][1]);
                float2 s2 = unpk(acc[m][2]);
                float2 s3 = unpk(acc[m][3]);
                float4 o0 = make_float4(bias8[0] + s0.x, bias8[1] + s0.y,
                                        bias8[2] + s1.x, bias8[3] + s1.y);
                float4 o1 = make_float4(bias8[4] + s2.x, bias8[5] + s2.y,
                                        bias8[6] + s3.x, bias8[7] + s3.y);
                float4* op = (float4*)(OUT + (size_t)mm * G3 + jbase + b * 8);
                op[0] = o0;
                op[1] = o1;
            }
        }
    }
}

// ---------------------------------------------------------------------------
// Persistent GRU scan (R6 exact — known-good 604us; dot loop un-interleaved).
// 128 CTAs x 384 threads, 2 batch rows per CTA. Thread j: gate row j, both rows.
// Whh row j: k[0,96) in 48 u64 regs, k[96,128) in SMEM.
// Roles: j<128 r-threads (+row-1 update), 128..255 z-threads,
// 256..383 n-threads (publish gh1, row-0 update).
// ---------------------------------------------------------------------------
__global__ void __launch_bounds__(G3, 1)
gru_scan(const float* __restrict__ Whh, const float* __restrict__ bhh,
         const int* __restrict__ x, int layer)
{
    extern __shared__ ulonglong2 Wsm2[];            // 8*384 ulonglong2 = 48 KB
    __shared__ __align__(16) float hbuf[2][2][HH];  // [buf][row][k]
    __shared__ float2 rp[HH], zp[HH];
    __shared__ float  ghn1[HH];                     // n-thread's gh1 for r tail
    __shared__ int    xs[2][TT];

    const int j  = threadIdx.x;
    const int b0 = blockIdx.x * 2, b1 = b0 + 1;
    const float* __restrict__ gxT = layer ? g_gx1 : g_G0;

    // --- init ---
    u64 wreg[48];
    {
        const ulonglong2* __restrict__ Wr = (const ulonglong2*)(Whh + j * HH);
#pragma unroll
        for (int q = 0; q < 24; q++) {              // k = 0..95
            ulonglong2 w = Wr[q];
            wreg[2 * q]     = w.x;
            wreg[2 * q + 1] = w.y;
        }
#pragma unroll
        for (int q = 0; q < 8; q++)                 // k = 96..127
            Wsm2[q * G3 + j] = Wr[24 + q];
    }
    for (int i = j; i < 2 * TT; i += G3) {
        int r = i >> 9, t = i & (TT - 1);
        ((int*)xs)[i] = x[(b0 + r) * TT + t];
    }
    if (j < HH) { hbuf[0][0][j] = 0.0f; hbuf[0][1][j] = 0.0f; }
    const float bh = bhh[j];
    __syncthreads();

    // preload gx for t=0 (role-specialized; uniform per warp)
    float gxa = 0.0f, gxb = 0.0f, gxn1 = 0.0f;
    {
        if (layer == 0) {
            gxa = __ldg(&gxT[xs[0][0] * G3 + j]);
            if (j < 2 * HH) gxb = __ldg(&gxT[xs[1][0] * G3 + j]);
            if (j < HH)     gxn1 = __ldg(&gxT[xs[1][0] * G3 + j + 2 * HH]);
        } else {
            gxa = __ldg(&gxT[(b0 * TT) * G3 + j]);
            if (j < 2 * HH) gxb = __ldg(&gxT[(b1 * TT) * G3 + j]);
            if (j < HH)     gxn1 = __ldg(&gxT[(b1 * TT) * G3 + j + 2 * HH]);
        }
    }

    for (int t = 0; t < TT; t++) {
        const int buf = t & 1;

        // prefetch next step's input gates (role-specialized)
        float ngxa = 0.0f, ngxb = 0.0f, ngxn1 = 0.0f;
        if (t + 1 < TT) {
            if (layer == 0) {
                ngxa = __ldg(&gxT[xs[0][t + 1] * G3 + j]);
                if (j < 2 * HH) ngxb = __ldg(&gxT[xs[1][t + 1] * G3 + j]);
                if (j < HH)     ngxn1 = __ldg(&gxT[xs[1][t + 1] * G3 + j + 2 * HH]);
            } else {
                ngxa = __ldg(&gxT[(b0 * TT + t + 1) * G3 + j]);
                if (j < 2 * HH) ngxb = __ldg(&gxT[(b1 * TT + t + 1) * G3 + j]);
                if (j < HH)     ngxn1 = __ldg(&gxT[(b1 * TT + t + 1) * G3 + j + 2 * HH]);
            }
        }

        // gh[j] for both rows: packed k-pair dot product (R6 loop shape)
        u64 a0 = 0ull, a1 = 0ull, a2 = 0ull, a3 = 0ull;
        const ulonglong2* __restrict__ h0p = (const ulonglong2*)hbuf[buf][0];
        const ulonglong2* __restrict__ h1p = (const ulonglong2*)hbuf[buf][1];
#pragma unroll
        for (int q = 0; q < 24; q++) {
            ulonglong2 ha = h0p[q];
            ulonglong2 hb = h1p[q];
            a0 = ffma2(wreg[2 * q],     ha.x, a0);
            a1 = ffma2(wreg[2 * q + 1], ha.y, a1);
            a2 = ffma2(wreg[2 * q],     hb.x, a2);
            a3 = ffma2(wreg[2 * q + 1], hb.y, a3);
        }
#pragma unroll
        for (int q = 0; q < 8; q++) {
            ulonglong2 w  = Wsm2[q * G3 + j];
            ulonglong2 ha = h0p[24 + q];
            ulonglong2 hb = h1p[24 + q];
            a0 = ffma2(w.x, ha.x, a0);
            a1 = ffma2(w.y, ha.y, a1);
            a2 = ffma2(w.x, hb.x, a2);
            a3 = ffma2(w.y, hb.y, a3);
        }
        float2 f0 = unpk(fadd2(a0, a1));
        float2 f1 = unpk(fadd2(a2, a3));
        const float gh0 = bh + (f0.x + f0.y);
        const float gh1 = bh + (f1.x + f1.y);

        // split roles
        if (j < HH) {
            // r-threads: produce r gates; after barrier do ROW-1 update
            float r0 = msig(gxa + gh0);
            float r1 = msig(gxb + gh1);
            rp[j] = make_float2(r0, r1);
            float hold1 = hbuf[buf][1][j];
            asm volatile("bar.sync 1, %0;" :: "n"(G3) : "memory");
            float z1 = zp[j].y;
            float g1 = ghn1[j];
            float n1 = mtanh(gxn1 + r1 * g1);
            float hn1 = n1 + z1 * (hold1 - n1);     // (1-z)*n + z*h
            hbuf[buf ^ 1][1][j] = hn1;
            if (layer == 0) {
                g_h0[(b1 * TT + t) * HH + j] = hn1;
            } else if (t == TT - 1) {
                g_hlast[b1 * HH + j] = hn1;
            }
        } else if (j < 2 * HH) {
            // z-threads: produce z gates, then idle
            zp[j - HH] = make_float2(msig(gxa + gh0), msig(gxb + gh1));
            asm volatile("bar.arrive 1, %0;" :: "n"(G3) : "memory");
        } else {
            // n-threads: publish gh1, after barrier do ROW-0 update
            const int i = j - 2 * HH;
            ghn1[i] = gh1;
            float hold0 = hbuf[buf][0][i];
            asm volatile("bar.sync 1, %0;" :: "n"(G3) : "memory");
            float2 rv = rp[i];
            float z0 = zp[i].x;
            float n0 = mtanh(gxa + rv.x * gh0);
            float hn0 = n0 + z0 * (hold0 - n0);
            hbuf[buf ^ 1][0][i] = hn0;
            if (layer == 0) {
                g_h0[(b0 * TT + t) * HH + i] = hn0;
            } else if (t == TT - 1) {
                g_hlast[b0 * HH + i] = hn0;
            }
        }
        __syncthreads();
        gxa = ngxa;
        gxb = ngxb;
        gxn1 = ngxn1;
    }
}

// ---------------------------------------------------------------------------
__global__ void __launch_bounds__(BB)
fc_kernel(const float* __restrict__ fcw, const float* __restrict__ fcb,
          float* __restrict__ out)
{
    __shared__ float ws[3 * HH];
    int b = threadIdx.x;
    for (int i = b; i < 3 * HH; i += BB) ws[i] = fcw[i];
    __syncthreads();
    float a0 = fcb[0], a1 = fcb[1], a2 = fcb[2];
#pragma unroll 4
    for (int k = 0; k < HH; k++) {
        float h = g_hlast[b * HH + k];
        h = h > 0.0f ? h : 0.0f;
        a0 = fmaf(h, ws[k], a0);
        a1 = fmaf(h, ws[HH + k], a1);
        a2 = fmaf(h, ws[2 * HH + k], a2);
    }
    out[b * 3 + 0] = a0;
    out[b * 3 + 1] = a1;
    out[b * 3 + 2] = a2;
}

// ---------------------------------------------------------------------------
extern "C" void kernel_launch(void* const* d_in, const int* in_sizes, int n_in,
                              void* d_out, int out_size)
{
    const int*   x    = (const int*)  d_in[0];
    const float* emb  = (const float*)d_in[1];
    const float* W_ih = (const float*)d_in[2];   // [2][384][128]
    const float* W_hh = (const float*)d_in[3];   // [2][384][128]
    const float* b_ih = (const float*)d_in[4];   // [2][384]
    const float* b_hh = (const float*)d_in[5];   // [2][384]
    const float* fc_w = (const float*)d_in[6];   // [3][128]
    const float* fc_b = (const float*)d_in[7];   // [3]
    float* out = (float*)d_out;

    const int smem_scan = 8 * G3 * (int)sizeof(ulonglong2);                   // 48 KB
    const int smem_gemm = (HH * WSTRIDE + HH * ASTRIDE) * (int)sizeof(float); // ~166 KB
    cudaFuncSetAttribute(gru_scan, cudaFuncAttributeMaxDynamicSharedMemorySize,
                         smem_scan);
    cudaFuncSetAttribute(gemm_tile, cudaFuncAttributeMaxDynamicSharedMemorySize,
                         smem_gemm);

    // 1) G0 = emb @ Wih0^T + b_ih0  (vocab-side precompute: V < B*T)
    gemm_tile<<<NCTA, 384, smem_gemm>>>(emb, W_ih, b_ih, VV, 0);
    // 2) layer-0 scan (gx gathered from G0), writes g_h0
    gru_scan<<<BB / 2, G3, smem_scan>>>(W_hh, b_hh, x, 0);
    // 3) gx1 = h0 @ Wih1^T + b_ih1
    gemm_tile<<<NCTA, 384, smem_gemm>>>(nullptr, W_ih + G3 * HH, b_ih + G3, BB * TT, 1);
    // 4) layer-1 scan, writes g_hlast
    gru_scan<<<BB / 2, G3, smem_scan>>>(W_hh + G3 * HH, b_hh + G3, x, 1);
    // 5) head
    fc_kernel<<<1, BB>>>(fc_w, fc_b, out);
}